// round 2
// baseline (speedup 1.0000x reference)
#include <cuda_runtime.h>
#include <math.h>

// Problem constants
#define TT 16      // tokens per batch
#define CC 256     // embed dim
#define HH 4       // heads
#define HS 64      // head size
#define FFD 1024   // ff dim
#define NT 512     // threads per CTA
#define PAD 260    // padded row stride (mult of 4, !=0 mod 32 for conflict spread)

// SMEM layout (floats):
//  xb  : 16*256          = 4096
//  hb  : 16*260          = 4160   (h after LN1; reused as attn output)
//  qb  : 16*260          = 4160   (q; reused as h2 after LN2)
//  kb  : 16*260          = 4160
//  vb  : 16*260          = 4160
//  ffb : 16*1024         = 16384
//  pb  : 16*256          = 4096   (partial-sum buffer for split-range GEMMs)
#define SMEM_FLOATS (4096 + 4*4160 + 16384 + 4096)
#define SMEM_BYTES (SMEM_FLOATS * 4)

__global__ __launch_bounds__(NT, 1)
void block_kernel(const float* __restrict__ x,
                  const float* __restrict__ Wq, const float* __restrict__ Wk,
                  const float* __restrict__ Wv, const float* __restrict__ Wo,
                  const float* __restrict__ bo,
                  const float* __restrict__ W1, const float* __restrict__ b1,
                  const float* __restrict__ W2, const float* __restrict__ b2,
                  const float* __restrict__ g1, const float* __restrict__ be1,
                  const float* __restrict__ g2, const float* __restrict__ be2,
                  float* __restrict__ out)
{
    extern __shared__ float sm[];
    float* xb  = sm;                 // [16][256]
    float* hb  = xb + TT*CC;         // [16][PAD]
    float* qb  = hb + TT*PAD;        // [16][PAD]
    float* kb  = qb + TT*PAD;        // [16][PAD]
    float* vb  = kb + TT*PAD;        // [16][PAD]
    float* ffb = vb + TT*PAD;        // [16][1024]
    float* pb  = ffb + TT*FFD;       // [16][256]

    const int b    = blockIdx.x;
    const int tid  = threadIdx.x;
    const int warp = tid >> 5;
    const int lane = tid & 31;

    const float* xg = x + (size_t)b * TT * CC;

    // ---- load x[b] into SMEM (vectorized) ----
    {
        const float4* src = (const float4*)xg;
        float4* dst = (float4*)xb;
        #pragma unroll
        for (int i = tid; i < TT*CC/4; i += NT) dst[i] = src[i];
    }
    __syncthreads();

    // ---- LN1: one warp per row ----
    {
        const int r = warp;   // 16 warps == 16 rows
        float s = 0.f, s2 = 0.f;
        #pragma unroll
        for (int c = lane; c < CC; c += 32) { float v = xb[r*CC + c]; s += v; s2 += v*v; }
        #pragma unroll
        for (int o = 16; o > 0; o >>= 1) {
            s  += __shfl_xor_sync(0xffffffffu, s,  o);
            s2 += __shfl_xor_sync(0xffffffffu, s2, o);
        }
        const float mu   = s * (1.0f/CC);
        const float var  = s2 * (1.0f/CC) - mu*mu;
        const float rstd = rsqrtf(var + 1e-5f);
        #pragma unroll
        for (int c = lane; c < CC; c += 32)
            hb[r*PAD + c] = (xb[r*CC + c] - mu) * rstd * g1[c] + be1[c];
    }
    __syncthreads();

    // ---- QKV projections: one output column per thread-iteration, 16-row reuse ----
    for (int j = tid; j < 3*CC; j += NT) {
        const float* W; float* dstbuf; int col;
        if (j < CC)        { W = Wq; col = j;        dstbuf = qb; }
        else if (j < 2*CC) { W = Wk; col = j - CC;   dstbuf = kb; }
        else               { W = Wv; col = j - 2*CC; dstbuf = vb; }
        const int h = col >> 6, d = col & 63;
        const float* wcol = W + (size_t)h * CC * HS + d;   // stride HS over c
        float acc[TT];
        #pragma unroll
        for (int r = 0; r < TT; r++) acc[r] = 0.f;
        #pragma unroll 2
        for (int c = 0; c < CC; c += 4) {
            const float w0 = wcol[(c+0)*HS];
            const float w1 = wcol[(c+1)*HS];
            const float w2 = wcol[(c+2)*HS];
            const float w3 = wcol[(c+3)*HS];
            #pragma unroll
            for (int r = 0; r < TT; r++) {
                const float4 hv = *(const float4*)&hb[r*PAD + c];
                acc[r] += hv.x*w0 + hv.y*w1 + hv.z*w2 + hv.w*w3;
            }
        }
        #pragma unroll
        for (int r = 0; r < TT; r++) dstbuf[r*PAD + col] = acc[r];
    }
    __syncthreads();

    // ---- attention: 64 (h,t) tasks, 4 per warp. attn output goes into hb. ----
    #pragma unroll
    for (int i = 0; i < 4; i++) {
        const int task = warp*4 + i;
        const int h = task >> 4, t = task & 15;
        const float* qrow = qb + t*PAD + h*HS;
        float sc = -INFINITY;
        if (lane < TT && lane <= t) {
            const float* krow = kb + lane*PAD + h*HS;
            float a = 0.f;
            #pragma unroll
            for (int c = 0; c < HS; c += 4) {
                const float4 qv = *(const float4*)&qrow[c];
                const float4 kv = *(const float4*)&krow[c];
                a += qv.x*kv.x + qv.y*kv.y + qv.z*kv.z + qv.w*kv.w;
            }
            sc = a * 0.0625f;   // C^-0.5 = 1/16  (reference scales by n_embed)
        }
        // softmax over lanes 0..15 (lanes >=16 carry garbage, never read)
        float m = sc;
        #pragma unroll
        for (int o = 8; o > 0; o >>= 1) m = fmaxf(m, __shfl_xor_sync(0xffffffffu, m, o, 16));
        const float e = __expf(sc - m);            // masked lanes: exp(-inf)=0
        float ssum = e;
        #pragma unroll
        for (int o = 8; o > 0; o >>= 1) ssum += __shfl_xor_sync(0xffffffffu, ssum, o, 16);
        const float wgt = e / ssum;
        // AV: each lane owns dims {lane, lane+32}
        float o0 = 0.f, o1 = 0.f;
        for (int s2 = 0; s2 <= t; s2++) {
            const float ws = __shfl_sync(0xffffffffu, wgt, s2);  // broadcast from lane s2 (<16)
            o0 += ws * vb[s2*PAD + h*HS + lane];
            o1 += ws * vb[s2*PAD + h*HS + lane + 32];
        }
        hb[t*PAD + h*HS + lane]      = o0;
        hb[t*PAD + h*HS + lane + 32] = o1;
    }
    __syncthreads();

    // ---- output projection + residual: x1 = x + attn @ Wo + bo (split c-range) ----
    {
        const int col = tid & (CC-1), half = tid >> 8;
        const float* wcol = Wo + col;                 // stride CC over c
        float acc[TT];
        #pragma unroll
        for (int r = 0; r < TT; r++) acc[r] = 0.f;
        const int c0 = half * (CC/2);
        #pragma unroll 2
        for (int c = c0; c < c0 + CC/2; c += 4) {
            const float w0 = wcol[(c+0)*CC];
            const float w1 = wcol[(c+1)*CC];
            const float w2 = wcol[(c+2)*CC];
            const float w3 = wcol[(c+3)*CC];
            #pragma unroll
            for (int r = 0; r < TT; r++) {
                const float4 av = *(const float4*)&hb[r*PAD + c];
                acc[r] += av.x*w0 + av.y*w1 + av.z*w2 + av.w*w3;
            }
        }
        if (half == 1) {
            #pragma unroll
            for (int r = 0; r < TT; r++) pb[r*CC + col] = acc[r];
        }
        __syncthreads();
        if (half == 0) {
            const float bias = bo[col];
            #pragma unroll
            for (int r = 0; r < TT; r++)
                xb[r*CC + col] = xb[r*CC + col] + bias + acc[r] + pb[r*CC + col];
        }
    }
    __syncthreads();

    // ---- LN2 on x1 (in xb) -> h2 into qb ----
    {
        const int r = warp;
        float s = 0.f, s2 = 0.f;
        #pragma unroll
        for (int c = lane; c < CC; c += 32) { float v = xb[r*CC + c]; s += v; s2 += v*v; }
        #pragma unroll
        for (int o = 16; o > 0; o >>= 1) {
            s  += __shfl_xor_sync(0xffffffffu, s,  o);
            s2 += __shfl_xor_sync(0xffffffffu, s2, o);
        }
        const float mu   = s * (1.0f/CC);
        const float var  = s2 * (1.0f/CC) - mu*mu;
        const float rstd = rsqrtf(var + 1e-5f);
        #pragma unroll
        for (int c = lane; c < CC; c += 32)
            qb[r*PAD + c] = (xb[r*CC + c] - mu) * rstd * g2[c] + be2[c];
    }
    __syncthreads();

    // ---- MLP1: ff = relu(h2 @ W1 + b1) ----
    for (int j = tid; j < FFD; j += NT) {   // 2 columns per thread
        const float* wcol = W1 + j;          // stride FFD over c
        float acc[TT];
        #pragma unroll
        for (int r = 0; r < TT; r++) acc[r] = 0.f;
        #pragma unroll 2
        for (int c = 0; c < CC; c += 4) {
            const float w0 = wcol[(c+0)*FFD];
            const float w1 = wcol[(c+1)*FFD];
            const float w2 = wcol[(c+2)*FFD];
            const float w3 = wcol[(c+3)*FFD];
            #pragma unroll
            for (int r = 0; r < TT; r++) {
                const float4 hv = *(const float4*)&qb[r*PAD + c];
                acc[r] += hv.x*w0 + hv.y*w1 + hv.z*w2 + hv.w*w3;
            }
        }
        const float bias = b1[j];
        #pragma unroll
        for (int r = 0; r < TT; r++) ffb[r*FFD + j] = fmaxf(acc[r] + bias, 0.f);
    }
    __syncthreads();

    // ---- MLP2 + residual: out = x1 + ff @ W2 + b2 (split j-range) ----
    {
        const int col = tid & (CC-1), half = tid >> 8;
        const float* wcol = W2 + col;               // stride CC over j
        float acc[TT];
        #pragma unroll
        for (int r = 0; r < TT; r++) acc[r] = 0.f;
        const int j0 = half * (FFD/2);
        #pragma unroll 2
        for (int j = j0; j < j0 + FFD/2; j += 4) {
            const float w0 = wcol[(j+0)*CC];
            const float w1 = wcol[(j+1)*CC];
            const float w2 = wcol[(j+2)*CC];
            const float w3 = wcol[(j+3)*CC];
            #pragma unroll
            for (int r = 0; r < TT; r++) {
                const float4 fv = *(const float4*)&ffb[r*FFD + j];
                acc[r] += fv.x*w0 + fv.y*w1 + fv.z*w2 + fv.w*w3;
            }
        }
        if (half == 1) {
            #pragma unroll
            for (int r = 0; r < TT; r++) pb[r*CC + col] = acc[r];
        }
        __syncthreads();
        if (half == 0) {
            const float bias = b2[col];
            float* og = out + (size_t)b * TT * CC;
            #pragma unroll
            for (int r = 0; r < TT; r++)
                og[r*CC + col] = xb[r*CC + col] + bias + acc[r] + pb[r*CC + col];
        }
    }
}

extern "C" void kernel_launch(void* const* d_in, const int* in_sizes, int n_in,
                              void* d_out, int out_size)
{
    const float* x   = (const float*)d_in[0];
    const float* Wq  = (const float*)d_in[1];
    const float* Wk  = (const float*)d_in[2];
    const float* Wv  = (const float*)d_in[3];
    const float* Wo  = (const float*)d_in[4];
    const float* bo  = (const float*)d_in[5];
    const float* W1  = (const float*)d_in[6];
    const float* b1  = (const float*)d_in[7];
    const float* W2  = (const float*)d_in[8];
    const float* b2  = (const float*)d_in[9];
    const float* g1  = (const float*)d_in[10];
    const float* be1 = (const float*)d_in[11];
    const float* g2  = (const float*)d_in[12];
    const float* be2 = (const float*)d_in[13];
    float* out = (float*)d_out;

    cudaFuncSetAttribute(block_kernel,
                         cudaFuncAttributeMaxDynamicSharedMemorySize, SMEM_BYTES);

    const int batches = 8192;  // B
    block_kernel<<<batches, NT, SMEM_BYTES>>>(
        x, Wq, Wk, Wv, Wo, bo, W1, b1, W2, b2, g1, be1, g2, be2, out);
}

// round 4
// speedup vs baseline: 1.9412x; 1.9412x over previous
#include <cuda_runtime.h>
#include <math.h>

#define TT 16      // tokens per batch
#define CC 256     // embed dim
#define HH 4       // heads
#define HS 64      // head size
#define FFD 1024   // ff dim
#define NT 512     // threads per CTA
#define PAD 260    // padded row stride for LN'd activations

// SMEM layout (floats)
#define SMEM_FLOATS (TT*CC + 4*TT*PAD + TT*FFD)
#define SMEM_BYTES (SMEM_FLOATS * 4)

__global__ __launch_bounds__(NT, 1)
void block_kernel(const float* __restrict__ x,
                  const float* __restrict__ Wq, const float* __restrict__ Wk,
                  const float* __restrict__ Wv, const float* __restrict__ Wo,
                  const float* __restrict__ bo,
                  const float* __restrict__ W1, const float* __restrict__ b1,
                  const float* __restrict__ W2, const float* __restrict__ b2,
                  const float* __restrict__ g1, const float* __restrict__ be1,
                  const float* __restrict__ g2, const float* __restrict__ be2,
                  float* __restrict__ out)
{
    extern __shared__ float sm[];
    float* xb  = sm;                 // [16][256]  residual stream
    float* hb  = xb + TT*CC;         // [16][PAD]  LN1 out; later attn out
    float* qb  = hb + TT*PAD;        // [16][PAD]  q; later LN2 out
    float* kb  = qb + TT*PAD;        // [16][PAD]
    float* vb  = kb + TT*PAD;        // [16][PAD]
    float* ffb = vb + TT*PAD;        // [16][1024]

    const int b    = blockIdx.x;
    const int tid  = threadIdx.x;
    const int warp = tid >> 5;
    const int lane = tid & 31;

    const float* xg = x + (size_t)b * TT * CC;

    // ---- load x[b] ----
    {
        const float4* src = (const float4*)xg;
        float4* dst = (float4*)xb;
        #pragma unroll
        for (int i = tid; i < TT*CC/4; i += NT) dst[i] = src[i];
    }
    __syncthreads();

    // ---- LN1: warp per row ----
    {
        const int r = warp;
        float s = 0.f, s2 = 0.f;
        #pragma unroll
        for (int c = lane; c < CC; c += 32) { float v = xb[r*CC + c]; s += v; s2 += v*v; }
        #pragma unroll
        for (int o = 16; o > 0; o >>= 1) {
            s  += __shfl_xor_sync(0xffffffffu, s,  o);
            s2 += __shfl_xor_sync(0xffffffffu, s2, o);
        }
        const float mu   = s * (1.0f/CC);
        const float var  = s2 * (1.0f/CC) - mu*mu;
        const float rstd = rsqrtf(var + 1e-5f);
        #pragma unroll
        for (int c = lane; c < CC; c += 32)
            hb[r*PAD + c] = (xb[r*CC + c] - mu) * rstd * g1[c] + be1[c];
    }
    __syncthreads();

    // ---- QKV: thread = (rowhalf, matrix, colgroup-of-4). 384 threads active. ----
    if (tid < 384) {
        const int rhalf = tid / 192;
        const int g     = tid % 192;
        const int mat   = g >> 6;
        const int col   = (g & 63) * 4;
        const float* W; float* dst;
        if (mat == 0)      { W = Wq; dst = qb; }
        else if (mat == 1) { W = Wk; dst = kb; }
        else               { W = Wv; dst = vb; }
        const int h = col >> 6, d = col & 63;
        const float* wp = W + (size_t)h*CC*HS + d;  // + c*HS, float4 over d
        const int r0 = rhalf * 8;
        float acc[4][8];
        #pragma unroll
        for (int i = 0; i < 4; i++)
            #pragma unroll
            for (int r = 0; r < 8; r++) acc[i][r] = 0.f;
        #pragma unroll 2
        for (int c = 0; c < CC; c += 4) {
            const float4 w0 = *(const float4*)(wp + (size_t)(c+0)*HS);
            const float4 w1 = *(const float4*)(wp + (size_t)(c+1)*HS);
            const float4 w2 = *(const float4*)(wp + (size_t)(c+2)*HS);
            const float4 w3 = *(const float4*)(wp + (size_t)(c+3)*HS);
            #pragma unroll
            for (int r = 0; r < 8; r++) {
                const float4 a = *(const float4*)&hb[(r0+r)*PAD + c];
                acc[0][r] += a.x*w0.x + a.y*w1.x + a.z*w2.x + a.w*w3.x;
                acc[1][r] += a.x*w0.y + a.y*w1.y + a.z*w2.y + a.w*w3.y;
                acc[2][r] += a.x*w0.z + a.y*w1.z + a.z*w2.z + a.w*w3.z;
                acc[3][r] += a.x*w0.w + a.y*w1.w + a.z*w2.w + a.w*w3.w;
            }
        }
        #pragma unroll
        for (int r = 0; r < 8; r++)
            #pragma unroll
            for (int i = 0; i < 4; i++)
                dst[(r0+r)*PAD + col + i] = acc[i][r];
    }
    __syncthreads();

    // ---- attention: 64 (h,t) tasks, 4 per warp; out -> hb ----
    #pragma unroll
    for (int i = 0; i < 4; i++) {
        const int task = warp*4 + i;
        const int h = task >> 4, t = task & 15;
        const float* qrow = qb + t*PAD + h*HS;
        float sc = -INFINITY;
        if (lane < TT && lane <= t) {
            const float* krow = kb + lane*PAD + h*HS;
            float a = 0.f;
            #pragma unroll
            for (int c = 0; c < HS; c += 4) {
                const float4 qv = *(const float4*)&qrow[c];
                const float4 kv = *(const float4*)&krow[c];
                a += qv.x*kv.x + qv.y*kv.y + qv.z*kv.z + qv.w*kv.w;
            }
            sc = a * 0.0625f;   // C^-0.5 (reference scales by n_embed)
        }
        float m = sc;
        #pragma unroll
        for (int o = 8; o > 0; o >>= 1) m = fmaxf(m, __shfl_xor_sync(0xffffffffu, m, o, 16));
        const float e = __expf(sc - m);
        float ssum = e;
        #pragma unroll
        for (int o = 8; o > 0; o >>= 1) ssum += __shfl_xor_sync(0xffffffffu, ssum, o, 16);
        const float wgt = e / ssum;
        float o0 = 0.f, o1 = 0.f;
        for (int s2 = 0; s2 <= t; s2++) {
            const float ws = __shfl_sync(0xffffffffu, wgt, s2);
            o0 += ws * vb[s2*PAD + h*HS + lane];
            o1 += ws * vb[s2*PAD + h*HS + lane + 32];
        }
        hb[t*PAD + h*HS + lane]      = o0;
        hb[t*PAD + h*HS + lane + 32] = o1;
    }
    __syncthreads();

    // ---- Wo + residual: thread = (rowhalf, colgroup-of-2). 256 threads. ----
    if (tid < 256) {
        const int rhalf = tid >> 7;
        const int col   = (tid & 127) * 2;
        const int r0    = rhalf * 8;
        const float* wp = Wo + col;  // + c*CC, float2 over cols
        float acc[2][8];
        #pragma unroll
        for (int i = 0; i < 2; i++)
            #pragma unroll
            for (int r = 0; r < 8; r++) acc[i][r] = 0.f;
        #pragma unroll 2
        for (int c = 0; c < CC; c += 4) {
            const float2 w0 = *(const float2*)(wp + (size_t)(c+0)*CC);
            const float2 w1 = *(const float2*)(wp + (size_t)(c+1)*CC);
            const float2 w2 = *(const float2*)(wp + (size_t)(c+2)*CC);
            const float2 w3 = *(const float2*)(wp + (size_t)(c+3)*CC);
            #pragma unroll
            for (int r = 0; r < 8; r++) {
                const float4 a = *(const float4*)&hb[(r0+r)*PAD + c];
                acc[0][r] += a.x*w0.x + a.y*w1.x + a.z*w2.x + a.w*w3.x;
                acc[1][r] += a.x*w0.y + a.y*w1.y + a.z*w2.y + a.w*w3.y;
            }
        }
        const float b0v = bo[col], b1v = bo[col+1];
        #pragma unroll
        for (int r = 0; r < 8; r++) {
            xb[(r0+r)*CC + col]     += b0v + acc[0][r];
            xb[(r0+r)*CC + col + 1] += b1v + acc[1][r];
        }
    }
    __syncthreads();

    // ---- LN2 on x1 (xb) -> qb ----
    {
        const int r = warp;
        float s = 0.f, s2 = 0.f;
        #pragma unroll
        for (int c = lane; c < CC; c += 32) { float v = xb[r*CC + c]; s += v; s2 += v*v; }
        #pragma unroll
        for (int o = 16; o > 0; o >>= 1) {
            s  += __shfl_xor_sync(0xffffffffu, s,  o);
            s2 += __shfl_xor_sync(0xffffffffu, s2, o);
        }
        const float mu   = s * (1.0f/CC);
        const float var  = s2 * (1.0f/CC) - mu*mu;
        const float rstd = rsqrtf(var + 1e-5f);
        #pragma unroll
        for (int c = lane; c < CC; c += 32)
            qb[r*PAD + c] = (xb[r*CC + c] - mu) * rstd * g2[c] + be2[c];
    }
    __syncthreads();

    // ---- MLP1: thread = (rowhalf, colgroup-of-4). 512 threads. ----
    {
        const int rhalf = tid >> 8;
        const int col   = (tid & 255) * 4;
        const int r0    = rhalf * 8;
        const float* wp = W1 + col;  // + c*FFD
        float acc[4][8];
        #pragma unroll
        for (int i = 0; i < 4; i++)
            #pragma unroll
            for (int r = 0; r < 8; r++) acc[i][r] = 0.f;
        #pragma unroll 2
        for (int c = 0; c < CC; c += 4) {
            const float4 w0 = *(const float4*)(wp + (size_t)(c+0)*FFD);
            const float4 w1 = *(const float4*)(wp + (size_t)(c+1)*FFD);
            const float4 w2 = *(const float4*)(wp + (size_t)(c+2)*FFD);
            const float4 w3 = *(const float4*)(wp + (size_t)(c+3)*FFD);
            #pragma unroll
            for (int r = 0; r < 8; r++) {
                const float4 a = *(const float4*)&qb[(r0+r)*PAD + c];
                acc[0][r] += a.x*w0.x + a.y*w1.x + a.z*w2.x + a.w*w3.x;
                acc[1][r] += a.x*w0.y + a.y*w1.y + a.z*w2.y + a.w*w3.y;
                acc[2][r] += a.x*w0.z + a.y*w1.z + a.z*w2.z + a.w*w3.z;
                acc[3][r] += a.x*w0.w + a.y*w1.w + a.z*w2.w + a.w*w3.w;
            }
        }
        const float4 bia = *(const float4*)(b1 + col);
        #pragma unroll
        for (int r = 0; r < 8; r++) {
            float4 o;
            o.x = fmaxf(acc[0][r] + bia.x, 0.f);
            o.y = fmaxf(acc[1][r] + bia.y, 0.f);
            o.z = fmaxf(acc[2][r] + bia.z, 0.f);
            o.w = fmaxf(acc[3][r] + bia.w, 0.f);
            *(float4*)&ffb[(r0+r)*FFD + col] = o;
        }
    }
    __syncthreads();

    // ---- MLP2 + residual: thread = (rowhalf, colgroup-of-2). 256 threads. ----
    if (tid < 256) {
        const int rhalf = tid >> 7;
        const int col   = (tid & 127) * 2;
        const int r0    = rhalf * 8;
        const float* wp = W2 + col;  // + j*CC
        float acc[2][8];
        #pragma unroll
        for (int i = 0; i < 2; i++)
            #pragma unroll
            for (int r = 0; r < 8; r++) acc[i][r] = 0.f;
        #pragma unroll 2
        for (int j = 0; j < FFD; j += 4) {
            const float2 w0 = *(const float2*)(wp + (size_t)(j+0)*CC);
            const float2 w1 = *(const float2*)(wp + (size_t)(j+1)*CC);
            const float2 w2 = *(const float2*)(wp + (size_t)(j+2)*CC);
            const float2 w3 = *(const float2*)(wp + (size_t)(j+3)*CC);
            #pragma unroll
            for (int r = 0; r < 8; r++) {
                const float4 a = *(const float4*)&ffb[(r0+r)*FFD + j];
                acc[0][r] += a.x*w0.x + a.y*w1.x + a.z*w2.x + a.w*w3.x;
                acc[1][r] += a.x*w0.y + a.y*w1.y + a.z*w2.y + a.w*w3.y;
            }
        }
        const float b0v = b2[col], b1v = b2[col+1];
        float* og = out + (size_t)b * TT * CC;
        #pragma unroll
        for (int r = 0; r < 8; r++) {
            og[(r0+r)*CC + col]     = xb[(r0+r)*CC + col]     + b0v + acc[0][r];
            og[(r0+r)*CC + col + 1] = xb[(r0+r)*CC + col + 1] + b1v + acc[1][r];
        }
    }
}

extern "C" void kernel_launch(void* const* d_in, const int* in_sizes, int n_in,
                              void* d_out, int out_size)
{
    const float* x   = (const float*)d_in[0];
    const float* Wq  = (const float*)d_in[1];
    const float* Wk  = (const float*)d_in[2];
    const float* Wv  = (const float*)d_in[3];
    const float* Wo  = (const float*)d_in[4];
    const float* bo  = (const float*)d_in[5];
    const float* W1  = (const float*)d_in[6];
    const float* b1  = (const float*)d_in[7];
    const float* W2  = (const float*)d_in[8];
    const float* b2  = (const float*)d_in[9];
    const float* g1  = (const float*)d_in[10];
    const float* be1 = (const float*)d_in[11];
    const float* g2  = (const float*)d_in[12];
    const float* be2 = (const float*)d_in[13];
    float* out = (float*)d_out;

    cudaFuncSetAttribute(block_kernel,
                         cudaFuncAttributeMaxDynamicSharedMemorySize, SMEM_BYTES);

    block_kernel<<<8192, NT, SMEM_BYTES>>>(
        x, Wq, Wk, Wv, Wo, bo, W1, b1, W2, b2, g1, be1, g2, be2, out);
}

// round 5
// speedup vs baseline: 2.4956x; 1.2856x over previous
#include <cuda_runtime.h>
#include <math.h>

#define TT 16      // tokens per batch
#define CC 256     // embed dim
#define HS 64      // head size
#define FFD 1024   // ff dim
#define NT 512     // threads per CTA
#define PADQ 260   // normal layout stride for q/k/v
#define S2C 516    // packed row-pair stride for C-wide bufs (2*256+4)
#define S2F 2052   // packed row-pair stride for FF-wide buf (2*1024+4)

typedef unsigned long long u64;

__device__ __forceinline__ u64 splat2(float v) {
    u64 r; asm("mov.b64 %0, {%1, %1};" : "=l"(r) : "f"(v)); return r;
}
__device__ __forceinline__ void fma2(u64& d, u64 a, u64 b) {
    asm("fma.rn.f32x2 %0, %1, %2, %0;" : "+l"(d) : "l"(a), "l"(b));
}
__device__ __forceinline__ void unpack2(float& lo, float& hi, u64 v) {
    asm("mov.b64 {%0, %1}, %2;" : "=f"(lo), "=f"(hi) : "l"(v));
}

// SMEM floats: xb 4096 + hb2 8*516 + q/k/v 3*16*260 + ffb2 8*2052 + pb 4096
#define SMEM_FLOATS (4096 + 8*S2C + 3*TT*PADQ + 8*S2F + 4096)
#define SMEM_BYTES (SMEM_FLOATS * 4)

__global__ __launch_bounds__(NT, 1)
void block_kernel(const float* __restrict__ x,
                  const float* __restrict__ Wq, const float* __restrict__ Wk,
                  const float* __restrict__ Wv, const float* __restrict__ Wo,
                  const float* __restrict__ bo,
                  const float* __restrict__ W1, const float* __restrict__ b1,
                  const float* __restrict__ W2, const float* __restrict__ b2,
                  const float* __restrict__ g1, const float* __restrict__ be1,
                  const float* __restrict__ g2, const float* __restrict__ be2,
                  float* __restrict__ out)
{
    extern __shared__ float sm[];
    float* xb   = sm;                  // [16][256]  residual stream (normal)
    float* hb2  = xb + TT*CC;          // [8][S2C]   row-pair packed: LN1 out / attn out / LN2 out
    float* qb   = hb2 + 8*S2C;         // [16][260]  q (normal)
    float* kb   = qb + TT*PADQ;        // [16][260]
    float* vb   = kb + TT*PADQ;        // [16][260]
    float* ffb2 = vb + TT*PADQ;        // [8][S2F]   row-pair packed ff
    float* pb   = ffb2 + 8*S2F;        // [16][256]  K-split partials

    const int b    = blockIdx.x;
    const int tid  = threadIdx.x;
    const int warp = tid >> 5;
    const int lane = tid & 31;

    const float* xg = x + (size_t)b * TT * CC;

    // ---- load x[b] ----
    {
        const float4* src = (const float4*)xg;
        float4* dst = (float4*)xb;
        #pragma unroll
        for (int i = tid; i < TT*CC/4; i += NT) dst[i] = src[i];
    }
    __syncthreads();

    // ---- LN1: warp per row -> packed hb2 ----
    {
        const int r = warp;
        float s = 0.f, s2 = 0.f;
        #pragma unroll
        for (int c = lane; c < CC; c += 32) { float v = xb[r*CC + c]; s += v; s2 += v*v; }
        #pragma unroll
        for (int o = 16; o > 0; o >>= 1) {
            s  += __shfl_xor_sync(0xffffffffu, s,  o);
            s2 += __shfl_xor_sync(0xffffffffu, s2, o);
        }
        const float mu   = s * (1.0f/CC);
        const float var  = s2 * (1.0f/CC) - mu*mu;
        const float rstd = rsqrtf(var + 1e-5f);
        #pragma unroll
        for (int c = lane; c < CC; c += 32)
            hb2[(r>>1)*S2C + c*2 + (r&1)] = (xb[r*CC + c] - mu) * rstd * g1[c] + be1[c];
    }
    __syncthreads();

    // ---- QKV: 384 threads = (rhalf, mat, colgroup-of-4), packed rows ----
    if (tid < 384) {
        const int rhalf = tid / 192;
        const int g     = tid % 192;
        const int mat   = g >> 6;
        const int col   = (g & 63) * 4;
        const float* W; float* dst;
        if (mat == 0)      { W = Wq; dst = qb; }
        else if (mat == 1) { W = Wk; dst = kb; }
        else               { W = Wv; dst = vb; }
        const int h = col >> 6, d = col & 63;
        const float* wp = W + (size_t)h*CC*HS + d;
        const int rp0 = rhalf * 4;
        u64 acc[4][4] = {};
        #pragma unroll 2
        for (int c = 0; c < CC; c += 2) {
            const float4 wA = *(const float4*)(wp + (size_t)(c  )*HS);
            const float4 wB = *(const float4*)(wp + (size_t)(c+1)*HS);
            const u64 sA0 = splat2(wA.x), sA1 = splat2(wA.y),
                      sA2 = splat2(wA.z), sA3 = splat2(wA.w);
            const u64 sB0 = splat2(wB.x), sB1 = splat2(wB.y),
                      sB2 = splat2(wB.z), sB3 = splat2(wB.w);
            #pragma unroll
            for (int rp = 0; rp < 4; rp++) {
                const ulonglong2 p = *(const ulonglong2*)&hb2[(rp0+rp)*S2C + c*2];
                fma2(acc[0][rp], p.x, sA0); fma2(acc[1][rp], p.x, sA1);
                fma2(acc[2][rp], p.x, sA2); fma2(acc[3][rp], p.x, sA3);
                fma2(acc[0][rp], p.y, sB0); fma2(acc[1][rp], p.y, sB1);
                fma2(acc[2][rp], p.y, sB2); fma2(acc[3][rp], p.y, sB3);
            }
        }
        #pragma unroll
        for (int rp = 0; rp < 4; rp++) {
            float4 lo4, hi4;
            unpack2(lo4.x, hi4.x, acc[0][rp]); unpack2(lo4.y, hi4.y, acc[1][rp]);
            unpack2(lo4.z, hi4.z, acc[2][rp]); unpack2(lo4.w, hi4.w, acc[3][rp]);
            const int r0 = 2*(rp0+rp);
            *(float4*)&dst[r0*PADQ + col]     = lo4;
            *(float4*)&dst[(r0+1)*PADQ + col] = hi4;
        }
    }
    __syncthreads();

    // ---- attention: 64 (h,t) tasks, 4 per warp; out -> packed hb2 ----
    #pragma unroll
    for (int i = 0; i < 4; i++) {
        const int task = warp*4 + i;
        const int h = task >> 4, t = task & 15;
        const float* qrow = qb + t*PADQ + h*HS;
        float sc = -INFINITY;
        if (lane < TT && lane <= t) {
            const float* krow = kb + lane*PADQ + h*HS;
            float a = 0.f;
            #pragma unroll
            for (int c = 0; c < HS; c += 4) {
                const float4 qv = *(const float4*)&qrow[c];
                const float4 kv = *(const float4*)&krow[c];
                a += qv.x*kv.x + qv.y*kv.y + qv.z*kv.z + qv.w*kv.w;
            }
            sc = a * 0.0625f;   // C^-0.5 (reference scales by n_embed)
        }
        float m = sc;
        #pragma unroll
        for (int o = 8; o > 0; o >>= 1) m = fmaxf(m, __shfl_xor_sync(0xffffffffu, m, o, 16));
        const float e = __expf(sc - m);
        float ssum = e;
        #pragma unroll
        for (int o = 8; o > 0; o >>= 1) ssum += __shfl_xor_sync(0xffffffffu, ssum, o, 16);
        const float wgt = e / ssum;
        float o0 = 0.f, o1 = 0.f;
        for (int s2 = 0; s2 <= t; s2++) {
            const float ws = __shfl_sync(0xffffffffu, wgt, s2);
            o0 += ws * vb[s2*PADQ + h*HS + lane];
            o1 += ws * vb[s2*PADQ + h*HS + lane + 32];
        }
        hb2[(t>>1)*S2C + (h*HS+lane)*2 + (t&1)]    = o0;
        hb2[(t>>1)*S2C + (h*HS+lane+32)*2 + (t&1)] = o1;
    }
    __syncthreads();

    // ---- Wo + residual: 512 threads = (khalf, rhalf, colgroup-of-2), K-split ----
    {
        const int khalf = tid >> 8;
        const int rhalf = (tid >> 7) & 1;
        const int col   = (tid & 127) * 2;
        const int rp0   = rhalf * 4;
        const int c0    = khalf * 128;
        const float* wp = Wo + col;
        u64 acc[2][4] = {};
        #pragma unroll 2
        for (int c = c0; c < c0 + 128; c += 2) {
            const float2 wA = *(const float2*)(wp + (size_t)(c  )*CC);
            const float2 wB = *(const float2*)(wp + (size_t)(c+1)*CC);
            const u64 sA0 = splat2(wA.x), sA1 = splat2(wA.y);
            const u64 sB0 = splat2(wB.x), sB1 = splat2(wB.y);
            #pragma unroll
            for (int rp = 0; rp < 4; rp++) {
                const ulonglong2 p = *(const ulonglong2*)&hb2[(rp0+rp)*S2C + c*2];
                fma2(acc[0][rp], p.x, sA0); fma2(acc[1][rp], p.x, sA1);
                fma2(acc[0][rp], p.y, sB0); fma2(acc[1][rp], p.y, sB1);
            }
        }
        if (khalf == 1) {
            #pragma unroll
            for (int rp = 0; rp < 4; rp++) {
                float l0,h0,l1,h1;
                unpack2(l0,h0,acc[0][rp]); unpack2(l1,h1,acc[1][rp]);
                const int r0 = 2*(rp0+rp);
                *(float2*)&pb[r0*CC + col]     = make_float2(l0, l1);
                *(float2*)&pb[(r0+1)*CC + col] = make_float2(h0, h1);
            }
        }
        __syncthreads();
        if (khalf == 0) {
            const float b0v = bo[col], b1v = bo[col+1];
            #pragma unroll
            for (int rp = 0; rp < 4; rp++) {
                float l0,h0,l1,h1;
                unpack2(l0,h0,acc[0][rp]); unpack2(l1,h1,acc[1][rp]);
                const int r0 = 2*(rp0+rp);
                xb[r0*CC+col]       += b0v + l0 + pb[r0*CC+col];
                xb[r0*CC+col+1]     += b1v + l1 + pb[r0*CC+col+1];
                xb[(r0+1)*CC+col]   += b0v + h0 + pb[(r0+1)*CC+col];
                xb[(r0+1)*CC+col+1] += b1v + h1 + pb[(r0+1)*CC+col+1];
            }
        }
    }
    __syncthreads();

    // ---- LN2 on x1 (xb) -> packed hb2 ----
    {
        const int r = warp;
        float s = 0.f, s2 = 0.f;
        #pragma unroll
        for (int c = lane; c < CC; c += 32) { float v = xb[r*CC + c]; s += v; s2 += v*v; }
        #pragma unroll
        for (int o = 16; o > 0; o >>= 1) {
            s  += __shfl_xor_sync(0xffffffffu, s,  o);
            s2 += __shfl_xor_sync(0xffffffffu, s2, o);
        }
        const float mu   = s * (1.0f/CC);
        const float var  = s2 * (1.0f/CC) - mu*mu;
        const float rstd = rsqrtf(var + 1e-5f);
        #pragma unroll
        for (int c = lane; c < CC; c += 32)
            hb2[(r>>1)*S2C + c*2 + (r&1)] = (xb[r*CC + c] - mu) * rstd * g2[c] + be2[c];
    }
    __syncthreads();

    // ---- MLP1: 512 threads = (rhalf, colgroup-of-4) -> packed ffb2 ----
    {
        const int rhalf = tid >> 8;
        const int col   = (tid & 255) * 4;
        const int rp0   = rhalf * 4;
        const float* wp = W1 + col;
        u64 acc[4][4] = {};
        #pragma unroll 2
        for (int c = 0; c < CC; c += 2) {
            const float4 wA = *(const float4*)(wp + (size_t)(c  )*FFD);
            const float4 wB = *(const float4*)(wp + (size_t)(c+1)*FFD);
            const u64 sA0 = splat2(wA.x), sA1 = splat2(wA.y),
                      sA2 = splat2(wA.z), sA3 = splat2(wA.w);
            const u64 sB0 = splat2(wB.x), sB1 = splat2(wB.y),
                      sB2 = splat2(wB.z), sB3 = splat2(wB.w);
            #pragma unroll
            for (int rp = 0; rp < 4; rp++) {
                const ulonglong2 p = *(const ulonglong2*)&hb2[(rp0+rp)*S2C + c*2];
                fma2(acc[0][rp], p.x, sA0); fma2(acc[1][rp], p.x, sA1);
                fma2(acc[2][rp], p.x, sA2); fma2(acc[3][rp], p.x, sA3);
                fma2(acc[0][rp], p.y, sB0); fma2(acc[1][rp], p.y, sB1);
                fma2(acc[2][rp], p.y, sB2); fma2(acc[3][rp], p.y, sB3);
            }
        }
        const float4 bia = *(const float4*)(b1 + col);
        #pragma unroll
        for (int rp = 0; rp < 4; rp++) {
            float l0,h0,l1,h1,l2,h2,l3,h3;
            unpack2(l0,h0,acc[0][rp]); unpack2(l1,h1,acc[1][rp]);
            unpack2(l2,h2,acc[2][rp]); unpack2(l3,h3,acc[3][rp]);
            float4 A, B;
            A.x = fmaxf(l0+bia.x, 0.f); A.y = fmaxf(h0+bia.x, 0.f);
            A.z = fmaxf(l1+bia.y, 0.f); A.w = fmaxf(h1+bia.y, 0.f);
            B.x = fmaxf(l2+bia.z, 0.f); B.y = fmaxf(h2+bia.z, 0.f);
            B.z = fmaxf(l3+bia.w, 0.f); B.w = fmaxf(h3+bia.w, 0.f);
            *(float4*)&ffb2[rp0*S2F + rp*S2F + col*2]     = A;
            *(float4*)&ffb2[rp0*S2F + rp*S2F + col*2 + 4] = B;
        }
    }
    __syncthreads();

    // ---- MLP2 + residual: 512 threads = (khalf, rhalf, colgroup-of-2), K-split ----
    {
        const int khalf = tid >> 8;
        const int rhalf = (tid >> 7) & 1;
        const int col   = (tid & 127) * 2;
        const int rp0   = rhalf * 4;
        const int j0    = khalf * 512;
        const float* wp = W2 + col;
        u64 acc[2][4] = {};
        #pragma unroll 2
        for (int j = j0; j < j0 + 512; j += 2) {
            const float2 wA = *(const float2*)(wp + (size_t)(j  )*CC);
            const float2 wB = *(const float2*)(wp + (size_t)(j+1)*CC);
            const u64 sA0 = splat2(wA.x), sA1 = splat2(wA.y);
            const u64 sB0 = splat2(wB.x), sB1 = splat2(wB.y);
            #pragma unroll
            for (int rp = 0; rp < 4; rp++) {
                const ulonglong2 p = *(const ulonglong2*)&ffb2[(rp0+rp)*S2F + j*2];
                fma2(acc[0][rp], p.x, sA0); fma2(acc[1][rp], p.x, sA1);
                fma2(acc[0][rp], p.y, sB0); fma2(acc[1][rp], p.y, sB1);
            }
        }
        if (khalf == 1) {
            #pragma unroll
            for (int rp = 0; rp < 4; rp++) {
                float l0,h0,l1,h1;
                unpack2(l0,h0,acc[0][rp]); unpack2(l1,h1,acc[1][rp]);
                const int r0 = 2*(rp0+rp);
                *(float2*)&pb[r0*CC + col]     = make_float2(l0, l1);
                *(float2*)&pb[(r0+1)*CC + col] = make_float2(h0, h1);
            }
        }
        __syncthreads();
        if (khalf == 0) {
            const float b0v = b2[col], b1v = b2[col+1];
            float* og = out + (size_t)b * TT * CC;
            #pragma unroll
            for (int rp = 0; rp < 4; rp++) {
                float l0,h0,l1,h1;
                unpack2(l0,h0,acc[0][rp]); unpack2(l1,h1,acc[1][rp]);
                const int r0 = 2*(rp0+rp);
                og[r0*CC+col]       = xb[r0*CC+col]       + b0v + l0 + pb[r0*CC+col];
                og[r0*CC+col+1]     = xb[r0*CC+col+1]     + b1v + l1 + pb[r0*CC+col+1];
                og[(r0+1)*CC+col]   = xb[(r0+1)*CC+col]   + b0v + h0 + pb[(r0+1)*CC+col];
                og[(r0+1)*CC+col+1] = xb[(r0+1)*CC+col+1] + b1v + h1 + pb[(r0+1)*CC+col+1];
            }
        }
    }
}

extern "C" void kernel_launch(void* const* d_in, const int* in_sizes, int n_in,
                              void* d_out, int out_size)
{
    const float* x   = (const float*)d_in[0];
    const float* Wq  = (const float*)d_in[1];
    const float* Wk  = (const float*)d_in[2];
    const float* Wv  = (const float*)d_in[3];
    const float* Wo  = (const float*)d_in[4];
    const float* bo  = (const float*)d_in[5];
    const float* W1  = (const float*)d_in[6];
    const float* b1  = (const float*)d_in[7];
    const float* W2  = (const float*)d_in[8];
    const float* b2  = (const float*)d_in[9];
    const float* g1  = (const float*)d_in[10];
    const float* be1 = (const float*)d_in[11];
    const float* g2  = (const float*)d_in[12];
    const float* be2 = (const float*)d_in[13];
    float* out = (float*)d_out;

    cudaFuncSetAttribute(block_kernel,
                         cudaFuncAttributeMaxDynamicSharedMemorySize, SMEM_BYTES);

    block_kernel<<<8192, NT, SMEM_BYTES>>>(
        x, Wq, Wk, Wv, Wo, bo, W1, b1, W2, b2, g1, be1, g2, be2, out);
}

// round 10
// speedup vs baseline: 2.4963x; 1.0003x over previous
#include <cuda_runtime.h>
#include <math.h>

#define TT 16      // tokens per batch
#define CC 256     // embed dim
#define HS 64      // head size
#define FFD 1024   // ff dim
#define NT 512     // threads per CTA
#define PADQ 260   // normal layout stride for q/k/v
#define S2C 516    // packed row-pair stride for C-wide bufs (2*256+4)
#define S2F 2052   // packed row-pair stride for FF-wide buf (2*1024+4)

typedef unsigned long long u64;

__device__ __forceinline__ u64 splat2(float v) {
    u64 r; asm("mov.b64 %0, {%1, %1};" : "=l"(r) : "f"(v)); return r;
}
__device__ __forceinline__ void fma2(u64& d, u64 a, u64 b) {
    asm("fma.rn.f32x2 %0, %1, %2, %0;" : "+l"(d) : "l"(a), "l"(b));
}
__device__ __forceinline__ void unpack2(float& lo, float& hi, u64 v) {
    asm("mov.b64 {%0, %1}, %2;" : "=f"(lo), "=f"(hi) : "l"(v));
}

// SMEM floats: xb 4096 + hb2 8*516 + q/k/v 3*16*260 + ffb2 8*2052 + pb 4096
#define SMEM_FLOATS (4096 + 8*S2C + 3*TT*PADQ + 8*S2F + 4096)
#define SMEM_BYTES (SMEM_FLOATS * 4)

__global__ __launch_bounds__(NT, 1)
void block_kernel(const float* __restrict__ x,
                  const float* __restrict__ Wq, const float* __restrict__ Wk,
                  const float* __restrict__ Wv, const float* __restrict__ Wo,
                  const float* __restrict__ bo,
                  const float* __restrict__ W1, const float* __restrict__ b1,
                  const float* __restrict__ W2, const float* __restrict__ b2,
                  const float* __restrict__ g1, const float* __restrict__ be1,
                  const float* __restrict__ g2, const float* __restrict__ be2,
                  float* __restrict__ out)
{
    extern __shared__ float sm[];
    float* xb   = sm;                  // [16][256]  residual stream (normal)
    float* hb2  = xb + TT*CC;          // [8][S2C]   row-pair packed: LN1 out / attn out / LN2 out
    float* qb   = hb2 + 8*S2C;         // [16][260]  q (normal)
    float* kb   = qb + TT*PADQ;        // [16][260]
    float* vb   = kb + TT*PADQ;        // [16][260]
    float* ffb2 = vb + TT*PADQ;        // [8][S2F]   row-pair packed ff
    float* pb   = ffb2 + 8*S2F;        // [16][256]  K-split partials

    const int b    = blockIdx.x;
    const int tid  = threadIdx.x;
    const int warp = tid >> 5;
    const int lane = tid & 31;

    const float* xg = x + (size_t)b * TT * CC;

    // ---- load x[b] ----
    {
        const float4* src = (const float4*)xg;
        float4* dst = (float4*)xb;
        #pragma unroll
        for (int i = tid; i < TT*CC/4; i += NT) dst[i] = src[i];
    }
    __syncthreads();

    // ---- LN1: warp per row -> packed hb2 ----
    {
        const int r = warp;
        float s = 0.f, s2 = 0.f;
        #pragma unroll
        for (int c = lane; c < CC; c += 32) { float v = xb[r*CC + c]; s += v; s2 += v*v; }
        #pragma unroll
        for (int o = 16; o > 0; o >>= 1) {
            s  += __shfl_xor_sync(0xffffffffu, s,  o);
            s2 += __shfl_xor_sync(0xffffffffu, s2, o);
        }
        const float mu   = s * (1.0f/CC);
        const float var  = s2 * (1.0f/CC) - mu*mu;
        const float rstd = rsqrtf(var + 1e-5f);
        #pragma unroll
        for (int c = lane; c < CC; c += 32)
            hb2[(r>>1)*S2C + c*2 + (r&1)] = (xb[r*CC + c] - mu) * rstd * g1[c] + be1[c];
    }
    __syncthreads();

    // ---- QKV: 384 threads = (rhalf, mat, colgroup-of-4), packed rows ----
    if (tid < 384) {
        const int rhalf = tid / 192;
        const int g     = tid % 192;
        const int mat   = g >> 6;
        const int col   = (g & 63) * 4;
        const float* W; float* dst;
        if (mat == 0)      { W = Wq; dst = qb; }
        else if (mat == 1) { W = Wk; dst = kb; }
        else               { W = Wv; dst = vb; }
        const int h = col >> 6, d = col & 63;
        const float* wp = W + (size_t)h*CC*HS + d;
        const int rp0 = rhalf * 4;
        u64 acc[4][4] = {};
        #pragma unroll 2
        for (int c = 0; c < CC; c += 2) {
            const float4 wA = *(const float4*)(wp + (size_t)(c  )*HS);
            const float4 wB = *(const float4*)(wp + (size_t)(c+1)*HS);
            const u64 sA0 = splat2(wA.x), sA1 = splat2(wA.y),
                      sA2 = splat2(wA.z), sA3 = splat2(wA.w);
            const u64 sB0 = splat2(wB.x), sB1 = splat2(wB.y),
                      sB2 = splat2(wB.z), sB3 = splat2(wB.w);
            #pragma unroll
            for (int rp = 0; rp < 4; rp++) {
                const ulonglong2 p = *(const ulonglong2*)&hb2[(rp0+rp)*S2C + c*2];
                fma2(acc[0][rp], p.x, sA0); fma2(acc[1][rp], p.x, sA1);
                fma2(acc[2][rp], p.x, sA2); fma2(acc[3][rp], p.x, sA3);
                fma2(acc[0][rp], p.y, sB0); fma2(acc[1][rp], p.y, sB1);
                fma2(acc[2][rp], p.y, sB2); fma2(acc[3][rp], p.y, sB3);
            }
        }
        #pragma unroll
        for (int rp = 0; rp < 4; rp++) {
            float4 lo4, hi4;
            unpack2(lo4.x, hi4.x, acc[0][rp]); unpack2(lo4.y, hi4.y, acc[1][rp]);
            unpack2(lo4.z, hi4.z, acc[2][rp]); unpack2(lo4.w, hi4.w, acc[3][rp]);
            const int r0 = 2*(rp0+rp);
            *(float4*)&dst[r0*PADQ + col]     = lo4;
            *(float4*)&dst[(r0+1)*PADQ + col] = hi4;
        }
    }
    __syncthreads();

    // ---- attention: 64 (h,t) tasks, 4 per warp; out -> packed hb2 ----
    #pragma unroll
    for (int i = 0; i < 4; i++) {
        const int task = warp*4 + i;
        const int h = task >> 4, t = task & 15;
        const float* qrow = qb + t*PADQ + h*HS;
        float sc = -INFINITY;
        if (lane < TT && lane <= t) {
            const float* krow = kb + lane*PADQ + h*HS;
            float a = 0.f;
            #pragma unroll
            for (int c = 0; c < HS; c += 4) {
                const float4 qv = *(const float4*)&qrow[c];
                const float4 kv = *(const float4*)&krow[c];
                a += qv.x*kv.x + qv.y*kv.y + qv.z*kv.z + qv.w*kv.w;
            }
            sc = a * 0.0625f;   // C^-0.5 (reference scales by n_embed)
        }
        float m = sc;
        #pragma unroll
        for (int o = 8; o > 0; o >>= 1) m = fmaxf(m, __shfl_xor_sync(0xffffffffu, m, o, 16));
        const float e = __expf(sc - m);
        float ssum = e;
        #pragma unroll
        for (int o = 8; o > 0; o >>= 1) ssum += __shfl_xor_sync(0xffffffffu, ssum, o, 16);
        const float wgt = e / ssum;
        float o0 = 0.f, o1 = 0.f;
        for (int s2 = 0; s2 <= t; s2++) {
            const float ws = __shfl_sync(0xffffffffu, wgt, s2);
            o0 += ws * vb[s2*PADQ + h*HS + lane];
            o1 += ws * vb[s2*PADQ + h*HS + lane + 32];
        }
        hb2[(t>>1)*S2C + (h*HS+lane)*2 + (t&1)]    = o0;
        hb2[(t>>1)*S2C + (h*HS+lane+32)*2 + (t&1)] = o1;
    }
    __syncthreads();

    // ---- Wo + residual: 512 threads = (khalf, rhalf, colgroup-of-2), K-split ----
    {
        const int khalf = tid >> 8;
        const int rhalf = (tid >> 7) & 1;
        const int col   = (tid & 127) * 2;
        const int rp0   = rhalf * 4;
        const int c0    = khalf * 128;
        const float* wp = Wo + col;
        u64 acc[2][4] = {};
        #pragma unroll 2
        for (int c = c0; c < c0 + 128; c += 2) {
            const float2 wA = *(const float2*)(wp + (size_t)(c  )*CC);
            const float2 wB = *(const float2*)(wp + (size_t)(c+1)*CC);
            const u64 sA0 = splat2(wA.x), sA1 = splat2(wA.y);
            const u64 sB0 = splat2(wB.x), sB1 = splat2(wB.y);
            #pragma unroll
            for (int rp = 0; rp < 4; rp++) {
                const ulonglong2 p = *(const ulonglong2*)&hb2[(rp0+rp)*S2C + c*2];
                fma2(acc[0][rp], p.x, sA0); fma2(acc[1][rp], p.x, sA1);
                fma2(acc[0][rp], p.y, sB0); fma2(acc[1][rp], p.y, sB1);
            }
        }
        if (khalf == 1) {
            #pragma unroll
            for (int rp = 0; rp < 4; rp++) {
                float l0,h0,l1,h1;
                unpack2(l0,h0,acc[0][rp]); unpack2(l1,h1,acc[1][rp]);
                const int r0 = 2*(rp0+rp);
                *(float2*)&pb[r0*CC + col]     = make_float2(l0, l1);
                *(float2*)&pb[(r0+1)*CC + col] = make_float2(h0, h1);
            }
        }
        __syncthreads();
        if (khalf == 0) {
            const float b0v = bo[col], b1v = bo[col+1];
            #pragma unroll
            for (int rp = 0; rp < 4; rp++) {
                float l0,h0,l1,h1;
                unpack2(l0,h0,acc[0][rp]); unpack2(l1,h1,acc[1][rp]);
                const int r0 = 2*(rp0+rp);
                xb[r0*CC+col]       += b0v + l0 + pb[r0*CC+col];
                xb[r0*CC+col+1]     += b1v + l1 + pb[r0*CC+col+1];
                xb[(r0+1)*CC+col]   += b0v + h0 + pb[(r0+1)*CC+col];
                xb[(r0+1)*CC+col+1] += b1v + h1 + pb[(r0+1)*CC+col+1];
            }
        }
    }
    __syncthreads();

    // ---- LN2 on x1 (xb) -> packed hb2 ----
    {
        const int r = warp;
        float s = 0.f, s2 = 0.f;
        #pragma unroll
        for (int c = lane; c < CC; c += 32) { float v = xb[r*CC + c]; s += v; s2 += v*v; }
        #pragma unroll
        for (int o = 16; o > 0; o >>= 1) {
            s  += __shfl_xor_sync(0xffffffffu, s,  o);
            s2 += __shfl_xor_sync(0xffffffffu, s2, o);
        }
        const float mu   = s * (1.0f/CC);
        const float var  = s2 * (1.0f/CC) - mu*mu;
        const float rstd = rsqrtf(var + 1e-5f);
        #pragma unroll
        for (int c = lane; c < CC; c += 32)
            hb2[(r>>1)*S2C + c*2 + (r&1)] = (xb[r*CC + c] - mu) * rstd * g2[c] + be2[c];
    }
    __syncthreads();

    // ---- MLP1: 512 threads = (rhalf, colgroup-of-4) -> packed ffb2 ----
    {
        const int rhalf = tid >> 8;
        const int col   = (tid & 255) * 4;
        const int rp0   = rhalf * 4;
        const float* wp = W1 + col;
        u64 acc[4][4] = {};
        #pragma unroll 2
        for (int c = 0; c < CC; c += 2) {
            const float4 wA = *(const float4*)(wp + (size_t)(c  )*FFD);
            const float4 wB = *(const float4*)(wp + (size_t)(c+1)*FFD);
            const u64 sA0 = splat2(wA.x), sA1 = splat2(wA.y),
                      sA2 = splat2(wA.z), sA3 = splat2(wA.w);
            const u64 sB0 = splat2(wB.x), sB1 = splat2(wB.y),
                      sB2 = splat2(wB.z), sB3 = splat2(wB.w);
            #pragma unroll
            for (int rp = 0; rp < 4; rp++) {
                const ulonglong2 p = *(const ulonglong2*)&hb2[(rp0+rp)*S2C + c*2];
                fma2(acc[0][rp], p.x, sA0); fma2(acc[1][rp], p.x, sA1);
                fma2(acc[2][rp], p.x, sA2); fma2(acc[3][rp], p.x, sA3);
                fma2(acc[0][rp], p.y, sB0); fma2(acc[1][rp], p.y, sB1);
                fma2(acc[2][rp], p.y, sB2); fma2(acc[3][rp], p.y, sB3);
            }
        }
        const float4 bia = *(const float4*)(b1 + col);
        #pragma unroll
        for (int rp = 0; rp < 4; rp++) {
            float l0,h0,l1,h1,l2,h2,l3,h3;
            unpack2(l0,h0,acc[0][rp]); unpack2(l1,h1,acc[1][rp]);
            unpack2(l2,h2,acc[2][rp]); unpack2(l3,h3,acc[3][rp]);
            float4 A, B;
            A.x = fmaxf(l0+bia.x, 0.f); A.y = fmaxf(h0+bia.x, 0.f);
            A.z = fmaxf(l1+bia.y, 0.f); A.w = fmaxf(h1+bia.y, 0.f);
            B.x = fmaxf(l2+bia.z, 0.f); B.y = fmaxf(h2+bia.z, 0.f);
            B.z = fmaxf(l3+bia.w, 0.f); B.w = fmaxf(h3+bia.w, 0.f);
            *(float4*)&ffb2[rp0*S2F + rp*S2F + col*2]     = A;
            *(float4*)&ffb2[rp0*S2F + rp*S2F + col*2 + 4] = B;
        }
    }
    __syncthreads();

    // ---- MLP2 + residual: 512 threads = (khalf, rhalf, colgroup-of-2), K-split ----
    {
        const int khalf = tid >> 8;
        const int rhalf = (tid >> 7) & 1;
        const int col   = (tid & 127) * 2;
        const int rp0   = rhalf * 4;
        const int j0    = khalf * 512;
        const float* wp = W2 + col;
        u64 acc[2][4] = {};
        #pragma unroll 2
        for (int j = j0; j < j0 + 512; j += 2) {
            const float2 wA = *(const float2*)(wp + (size_t)(j  )*CC);
            const float2 wB = *(const float2*)(wp + (size_t)(j+1)*CC);
            const u64 sA0 = splat2(wA.x), sA1 = splat2(wA.y);
            const u64 sB0 = splat2(wB.x), sB1 = splat2(wB.y);
            #pragma unroll
            for (int rp = 0; rp < 4; rp++) {
                const ulonglong2 p = *(const ulonglong2*)&ffb2[(rp0+rp)*S2F + j*2];
                fma2(acc[0][rp], p.x, sA0); fma2(acc[1][rp], p.x, sA1);
                fma2(acc[0][rp], p.y, sB0); fma2(acc[1][rp], p.y, sB1);
            }
        }
        if (khalf == 1) {
            #pragma unroll
            for (int rp = 0; rp < 4; rp++) {
                float l0,h0,l1,h1;
                unpack2(l0,h0,acc[0][rp]); unpack2(l1,h1,acc[1][rp]);
                const int r0 = 2*(rp0+rp);
                *(float2*)&pb[r0*CC + col]     = make_float2(l0, l1);
                *(float2*)&pb[(r0+1)*CC + col] = make_float2(h0, h1);
            }
        }
        __syncthreads();
        if (khalf == 0) {
            const float b0v = b2[col], b1v = b2[col+1];
            float* og = out + (size_t)b * TT * CC;
            #pragma unroll
            for (int rp = 0; rp < 4; rp++) {
                float l0,h0,l1,h1;
                unpack2(l0,h0,acc[0][rp]); unpack2(l1,h1,acc[1][rp]);
                const int r0 = 2*(rp0+rp);
                og[r0*CC+col]       = xb[r0*CC+col]       + b0v + l0 + pb[r0*CC+col];
                og[r0*CC+col+1]     = xb[r0*CC+col+1]     + b1v + l1 + pb[r0*CC+col+1];
                og[(r0+1)*CC+col]   = xb[(r0+1)*CC+col]   + b0v + h0 + pb[(r0+1)*CC+col];
                og[(r0+1)*CC+col+1] = xb[(r0+1)*CC+col+1] + b1v + h1 + pb[(r0+1)*CC+col+1];
            }
        }
    }
}

extern "C" void kernel_launch(void* const* d_in, const int* in_sizes, int n_in,
                              void* d_out, int out_size)
{
    const float* x   = (const float*)d_in[0];
    const float* Wq  = (const float*)d_in[1];
    const float* Wk  = (const float*)d_in[2];
    const float* Wv  = (const float*)d_in[3];
    const float* Wo  = (const float*)d_in[4];
    const float* bo  = (const float*)d_in[5];
    const float* W1  = (const float*)d_in[6];
    const float* b1  = (const float*)d_in[7];
    const float* W2  = (const float*)d_in[8];
    const float* b2  = (const float*)d_in[9];
    const float* g1  = (const float*)d_in[10];
    const float* be1 = (const float*)d_in[11];
    const float* g2  = (const float*)d_in[12];
    const float* be2 = (const float*)d_in[13];
    float* out = (float*)d_out;

    cudaFuncSetAttribute(block_kernel,
                         cudaFuncAttributeMaxDynamicSharedMemorySize, SMEM_BYTES);

    block_kernel<<<8192, NT, SMEM_BYTES>>>(
        x, Wq, Wk, Wv, Wo, bo, W1, b1, W2, b2, g1, be1, g2, be2, out);
}